// round 1
// baseline (speedup 1.0000x reference)
#include <cuda_runtime.h>
#include <cstdint>

// Problem constants (fixed by setup_inputs)
#define BSZ   16
#define N1    4096
#define N2    1024
#define C1    128
#define C2    256
#define CIN   384
#define CH    256
#define COUT  256
#define MTOT  (BSZ * N1)   // 65536 rows

// Scratch (static __device__ — allocation-free per harness rules)
__device__ float g_interp[MTOT * C2];   // 67 MB
__device__ float g_hidden[MTOT * CH];   // 67 MB

// ---------------------------------------------------------------------------
// Kernel 1: 3-NN search + inverse-distance interpolation.
// One warp per query point; 8 warps/block share one batch's xyz2 in SMEM.
// Distance uses the reference formula  |q|^2 - 2 q.p + |p|^2  to keep
// near-tie orderings correlated with the reference implementation.
// ---------------------------------------------------------------------------
__global__ __launch_bounds__(256)
void knn_interp_kernel(const float* __restrict__ xyz1,
                       const float* __restrict__ xyz2,
                       const float* __restrict__ fea2)
{
    __shared__ float sx[N2], sy[N2], sz[N2], spp[N2];

    const int b       = blockIdx.x >> 9;          // 512 blocks per batch
    const int pt_base = (blockIdx.x & 511) * 8;   // 8 warps -> 8 points

    const float* x2 = xyz2 + (size_t)b * N2 * 3;
    for (int i = threadIdx.x; i < N2; i += blockDim.x) {
        float px = x2[i * 3 + 0];
        float py = x2[i * 3 + 1];
        float pz = x2[i * 3 + 2];
        sx[i] = px; sy[i] = py; sz[i] = pz;
        spp[i] = px * px + py * py + pz * pz;
    }
    __syncthreads();

    const int warp = threadIdx.x >> 5;
    const int lane = threadIdx.x & 31;
    const int n    = pt_base + warp;
    const int row  = b * N1 + n;

    const float* q = xyz1 + (size_t)row * 3;
    const float qx = q[0], qy = q[1], qz = q[2];
    const float qq = qx * qx + qy * qy + qz * qz;

    // per-lane top-3 (ascending)
    float d0 = 1e30f, d1 = 1e30f, d2 = 1e30f;
    int   i0 = 0,     i1 = 0,     i2 = 0;

    for (int j = lane; j < N2; j += 32) {
        float dot = qx * sx[j] + qy * sy[j] + qz * sz[j];
        float d   = (qq - 2.0f * dot) + spp[j];
        if (d < d2) {
            if (d < d1) {
                d2 = d1; i2 = i1;
                if (d < d0) { d1 = d0; i1 = i0; d0 = d; i0 = j; }
                else        { d1 = d;  i1 = j; }
            } else { d2 = d; i2 = j; }
        }
    }

    // butterfly merge of sorted triples: insert the partner's 3 candidates
    #pragma unroll
    for (int off = 16; off; off >>= 1) {
        float e[3]; int ei[3];
        e[0]  = __shfl_xor_sync(0xffffffffu, d0, off);
        e[1]  = __shfl_xor_sync(0xffffffffu, d1, off);
        e[2]  = __shfl_xor_sync(0xffffffffu, d2, off);
        ei[0] = __shfl_xor_sync(0xffffffffu, i0, off);
        ei[1] = __shfl_xor_sync(0xffffffffu, i1, off);
        ei[2] = __shfl_xor_sync(0xffffffffu, i2, off);
        #pragma unroll
        for (int k = 0; k < 3; k++) {
            float d = e[k]; int idx = ei[k];
            if (d < d2) {
                if (d < d1) {
                    d2 = d1; i2 = i1;
                    if (d < d0) { d1 = d0; i1 = i0; d0 = d; i0 = idx; }
                    else        { d1 = d;  i1 = idx; }
                } else { d2 = d; i2 = idx; }
            }
        }
    }

    // inverse-distance weights (matches reference: 1/(d+1e-8), normalized)
    const float r0 = 1.0f / (d0 + 1e-8f);
    const float r1 = 1.0f / (d1 + 1e-8f);
    const float r2 = 1.0f / (d2 + 1e-8f);
    const float inv_s = 1.0f / (r0 + r1 + r2);
    const float w0 = r0 * inv_s, w1 = r1 * inv_s, w2 = r2 * inv_s;

    const float* f2 = fea2 + (size_t)b * N2 * C2;
    const float* p0 = f2 + (size_t)i0 * C2;
    const float* p1 = f2 + (size_t)i1 * C2;
    const float* p2 = f2 + (size_t)i2 * C2;
    float* outp = g_interp + (size_t)row * C2;

    #pragma unroll
    for (int c = lane; c < C2; c += 32)
        outp[c] = w0 * p0[c] + w1 * p1[c] + w2 * p2[c];
}

// ---------------------------------------------------------------------------
// Tiled fp32 GEMM:  out[M,256] = ReLU(A[M,K] @ W[K,256] + bias)
// 64x64 block tile, BK=16, 256 threads, 4x4 per thread.
// CONCAT=true: A row = [fea1 row (128) | g_interp row (256)]  (K=384)
// ---------------------------------------------------------------------------
template <int K_TOT, bool CONCAT>
__global__ __launch_bounds__(256)
void mlp_gemm_kernel(const float* __restrict__ A0,   // fea1 or hidden
                     const float* __restrict__ A1,   // interp (CONCAT only)
                     const float* __restrict__ W,    // [K_TOT, 256]
                     const float* __restrict__ bias, // [256]
                     float* __restrict__ outp)       // [M, 256]
{
    __shared__ float As[16][64];
    __shared__ float Bs[16][64];

    const int tid = threadIdx.x;
    const int tx  = tid & 15;        // 0..15 -> 4 cols each
    const int ty  = tid >> 4;        // 0..15 -> 4 rows each
    const int rowBase = blockIdx.y * 64;
    const int colBase = blockIdx.x * 64;

    float acc[4][4];
    #pragma unroll
    for (int i = 0; i < 4; i++)
        #pragma unroll
        for (int j = 0; j < 4; j++) acc[i][j] = 0.0f;

    for (int kt = 0; kt < K_TOT; kt += 16) {
        // A tile: 64 rows x 16 k, stored transposed As[k][m]
        #pragma unroll
        for (int i = 0; i < 4; i++) {
            int e  = tid + i * 256;
            int r  = e >> 4;
            int kk = e & 15;
            int gr = rowBase + r;
            int gk = kt + kk;
            float v;
            if (CONCAT) {
                // gk<128 vs >=128 is uniform per 16-wide k-tile (C1 % 16 == 0)
                v = (gk < C1) ? A0[(size_t)gr * C1 + gk]
                              : A1[(size_t)gr * C2 + (gk - C1)];
            } else {
                v = A0[(size_t)gr * K_TOT + gk];
            }
            As[kk][r] = v;
        }
        // B tile: 16 k x 64 n
        #pragma unroll
        for (int i = 0; i < 4; i++) {
            int e  = tid + i * 256;
            int kk = e >> 6;
            int nn = e & 63;
            Bs[kk][nn] = W[(size_t)(kt + kk) * 256 + colBase + nn];
        }
        __syncthreads();

        #pragma unroll
        for (int kk = 0; kk < 16; kk++) {
            float a[4], bf[4];
            #pragma unroll
            for (int i = 0; i < 4; i++) a[i] = As[kk][ty * 4 + i];
            #pragma unroll
            for (int j = 0; j < 4; j++) bf[j] = Bs[kk][tx * 4 + j];
            #pragma unroll
            for (int i = 0; i < 4; i++)
                #pragma unroll
                for (int j = 0; j < 4; j++)
                    acc[i][j] = fmaf(a[i], bf[j], acc[i][j]);
        }
        __syncthreads();
    }

    // epilogue: bias + ReLU
    #pragma unroll
    for (int i = 0; i < 4; i++) {
        int gr = rowBase + ty * 4 + i;
        #pragma unroll
        for (int j = 0; j < 4; j++) {
            int gc = colBase + tx * 4 + j;
            float v = acc[i][j] + bias[gc];
            outp[(size_t)gr * 256 + gc] = fmaxf(v, 0.0f);
        }
    }
}

// ---------------------------------------------------------------------------
extern "C" void kernel_launch(void* const* d_in, const int* in_sizes, int n_in,
                              void* d_out, int out_size)
{
    const float* xyz1 = (const float*)d_in[0];   // [16,4096,3]
    const float* xyz2 = (const float*)d_in[1];   // [16,1024,3]
    const float* fea1 = (const float*)d_in[2];   // [16,4096,128]
    const float* fea2 = (const float*)d_in[3];   // [16,1024,256]
    const float* W1   = (const float*)d_in[4];   // [384,256]
    const float* b1   = (const float*)d_in[5];   // [256]
    const float* W2   = (const float*)d_in[6];   // [256,256]
    const float* b2   = (const float*)d_in[7];   // [256]
    float* out        = (float*)d_out;           // [16,4096,256]

    float* interp;
    float* hidden;
    cudaGetSymbolAddress((void**)&interp, g_interp);
    cudaGetSymbolAddress((void**)&hidden, g_hidden);

    // 1) 3-NN + interpolation -> g_interp
    knn_interp_kernel<<<MTOT / 8, 256>>>(xyz1, xyz2, fea2);

    // 2) hidden = ReLU([fea1|interp] @ W1 + b1)
    {
        dim3 grid(COUT / 64, MTOT / 64);   // (4, 1024)
        mlp_gemm_kernel<CIN, true><<<grid, 256>>>(fea1, interp, W1, b1, hidden);
    }

    // 3) out = ReLU(hidden @ W2 + b2)
    {
        dim3 grid(COUT / 64, MTOT / 64);
        mlp_gemm_kernel<CH, false><<<grid, 256>>>(hidden, nullptr, W2, b2, out);
    }
}

// round 3
// speedup vs baseline: 3.0809x; 3.0809x over previous
#include <cuda_runtime.h>
#include <cuda_bf16.h>
#include <cstdint>

// Problem constants (fixed by setup_inputs)
#define BSZ   16
#define N1    4096
#define N2    1024
#define C1    128
#define C2    256
#define CIN   384
#define CH    256
#define MTOT  (BSZ * N1)   // 65536 rows

// ---------------------------------------------------------------------------
// Scratch (static __device__ — allocation-free per harness rules)
// All GEMM operands live as bf16 hi/lo pairs.
// ---------------------------------------------------------------------------
__device__ __align__(16) __nv_bfloat16 g_fea1_hi[MTOT * C1];
__device__ __align__(16) __nv_bfloat16 g_fea1_lo[MTOT * C1];
__device__ __align__(16) __nv_bfloat16 g_interp_hi[MTOT * C2];
__device__ __align__(16) __nv_bfloat16 g_interp_lo[MTOT * C2];
__device__ __align__(16) __nv_bfloat16 g_hidden_hi[MTOT * CH];
__device__ __align__(16) __nv_bfloat16 g_hidden_lo[MTOT * CH];
__device__ __align__(16) __nv_bfloat16 g_w1t_hi[256 * CIN];   // W1^T [N][K]
__device__ __align__(16) __nv_bfloat16 g_w1t_lo[256 * CIN];
__device__ __align__(16) __nv_bfloat16 g_w2t_hi[256 * CH];
__device__ __align__(16) __nv_bfloat16 g_w2t_lo[256 * CH];

// ---------------------------------------------------------------------------
// PTX helpers (sm_80-era only: cp.async / ldmatrix / mma.sync — all valid
// at compute_100 without the 'a' suffix)
// ---------------------------------------------------------------------------
__device__ __forceinline__ uint32_t smem_to_u32(const void* p) {
    uint32_t a;
    asm("{ .reg .u64 t; cvta.to.shared.u64 t, %1; cvt.u32.u64 %0, t; }"
        : "=r"(a) : "l"(p));
    return a;
}

__device__ __forceinline__ void cp_async16(uint32_t dst_smem, const void* src) {
    asm volatile("cp.async.cg.shared.global [%0], [%1], 16;"
                 :: "r"(dst_smem), "l"(src));
}
#define CP_COMMIT()  asm volatile("cp.async.commit_group;")
#define CP_WAIT(n)   asm volatile("cp.async.wait_group %0;" :: "n"(n))

__device__ __forceinline__ void ldsm_x4(uint32_t& r0, uint32_t& r1,
                                        uint32_t& r2, uint32_t& r3, uint32_t addr) {
    asm volatile("ldmatrix.sync.aligned.m8n8.x4.shared.b16 {%0,%1,%2,%3}, [%4];"
                 : "=r"(r0), "=r"(r1), "=r"(r2), "=r"(r3) : "r"(addr));
}
__device__ __forceinline__ void ldsm_x2(uint32_t& r0, uint32_t& r1, uint32_t addr) {
    asm volatile("ldmatrix.sync.aligned.m8n8.x2.shared.b16 {%0,%1}, [%2];"
                 : "=r"(r0), "=r"(r1) : "r"(addr));
}

__device__ __forceinline__ void mma_bf16(float* c, const uint32_t* a, const uint32_t* b) {
    asm volatile(
        "mma.sync.aligned.m16n8k16.row.col.f32.bf16.bf16.f32 "
        "{%0,%1,%2,%3}, {%4,%5,%6,%7}, {%8,%9}, {%0,%1,%2,%3};"
        : "+f"(c[0]), "+f"(c[1]), "+f"(c[2]), "+f"(c[3])
        : "r"(a[0]), "r"(a[1]), "r"(a[2]), "r"(a[3]), "r"(b[0]), "r"(b[1]));
}

__device__ __forceinline__ void split_bf16(float v, __nv_bfloat16& h, __nv_bfloat16& l) {
    h = __float2bfloat16_rn(v);
    l = __float2bfloat16_rn(v - __bfloat162float(h));
}

// ---------------------------------------------------------------------------
// Kernel 0a: weight transpose + bf16 hi/lo split.  W[K,256] -> Wt[256,K]
// ---------------------------------------------------------------------------
__global__ void wsplit_kernel(const float* __restrict__ W,
                              __nv_bfloat16* __restrict__ hi,
                              __nv_bfloat16* __restrict__ lo, int K)
{
    int k = blockIdx.x;
    int n = threadIdx.x;
    float w = W[(size_t)k * 256 + n];
    __nv_bfloat16 h, l;
    split_bf16(w, h, l);
    hi[(size_t)n * K + k] = h;
    lo[(size_t)n * K + k] = l;
}

// ---------------------------------------------------------------------------
// Kernel 0b: fea1 fp32 -> bf16 hi/lo (same layout), 4 elems/thread
// ---------------------------------------------------------------------------
__global__ __launch_bounds__(256)
void asplit_kernel(const float* __restrict__ src,
                   __nv_bfloat16* __restrict__ hi,
                   __nv_bfloat16* __restrict__ lo)
{
    size_t i4 = (size_t)blockIdx.x * 256 + threadIdx.x;
    float4 v = *(const float4*)(src + i4 * 4);
    __nv_bfloat16 h[4], l[4];
    split_bf16(v.x, h[0], l[0]);
    split_bf16(v.y, h[1], l[1]);
    split_bf16(v.z, h[2], l[2]);
    split_bf16(v.w, h[3], l[3]);
    *(__nv_bfloat162*)(hi + i4 * 4)     = __nv_bfloat162(h[0], h[1]);
    *(__nv_bfloat162*)(hi + i4 * 4 + 2) = __nv_bfloat162(h[2], h[3]);
    *(__nv_bfloat162*)(lo + i4 * 4)     = __nv_bfloat162(l[0], l[1]);
    *(__nv_bfloat162*)(lo + i4 * 4 + 2) = __nv_bfloat162(l[2], l[3]);
}

// ---------------------------------------------------------------------------
// Kernel 1: 3-NN search + inverse-distance interpolation -> bf16 hi/lo
// ---------------------------------------------------------------------------
__global__ __launch_bounds__(256)
void knn_interp_kernel(const float* __restrict__ xyz1,
                       const float* __restrict__ xyz2,
                       const float* __restrict__ fea2)
{
    __shared__ float sx[N2], sy[N2], sz[N2], spp[N2];

    const int b       = blockIdx.x >> 9;
    const int pt_base = (blockIdx.x & 511) * 8;

    const float* x2 = xyz2 + (size_t)b * N2 * 3;
    for (int i = threadIdx.x; i < N2; i += blockDim.x) {
        float px = x2[i * 3 + 0];
        float py = x2[i * 3 + 1];
        float pz = x2[i * 3 + 2];
        sx[i] = px; sy[i] = py; sz[i] = pz;
        spp[i] = px * px + py * py + pz * pz;
    }
    __syncthreads();

    const int warp = threadIdx.x >> 5;
    const int lane = threadIdx.x & 31;
    const int row  = b * N1 + pt_base + warp;

    const float* q = xyz1 + (size_t)row * 3;
    const float qx = q[0], qy = q[1], qz = q[2];
    const float qq = qx * qx + qy * qy + qz * qz;

    float d0 = 1e30f, d1 = 1e30f, d2 = 1e30f;
    int   i0 = 0,     i1 = 0,     i2 = 0;

    for (int j = lane; j < N2; j += 32) {
        float dot = qx * sx[j] + qy * sy[j] + qz * sz[j];
        float d   = (qq - 2.0f * dot) + spp[j];
        if (d < d2) {
            if (d < d1) {
                d2 = d1; i2 = i1;
                if (d < d0) { d1 = d0; i1 = i0; d0 = d; i0 = j; }
                else        { d1 = d;  i1 = j; }
            } else { d2 = d; i2 = j; }
        }
    }

    #pragma unroll
    for (int off = 16; off; off >>= 1) {
        float e[3]; int ei[3];
        e[0]  = __shfl_xor_sync(0xffffffffu, d0, off);
        e[1]  = __shfl_xor_sync(0xffffffffu, d1, off);
        e[2]  = __shfl_xor_sync(0xffffffffu, d2, off);
        ei[0] = __shfl_xor_sync(0xffffffffu, i0, off);
        ei[1] = __shfl_xor_sync(0xffffffffu, i1, off);
        ei[2] = __shfl_xor_sync(0xffffffffu, i2, off);
        #pragma unroll
        for (int k = 0; k < 3; k++) {
            float d = e[k]; int idx = ei[k];
            if (d < d2) {
                if (d < d1) {
                    d2 = d1; i2 = i1;
                    if (d < d0) { d1 = d0; i1 = i0; d0 = d; i0 = idx; }
                    else        { d1 = d;  i1 = idx; }
                } else { d2 = d; i2 = idx; }
            }
        }
    }

    const float r0 = 1.0f / (d0 + 1e-8f);
    const float r1 = 1.0f / (d1 + 1e-8f);
    const float r2 = 1.0f / (d2 + 1e-8f);
    const float inv_s = 1.0f / (r0 + r1 + r2);
    const float w0 = r0 * inv_s, w1 = r1 * inv_s, w2 = r2 * inv_s;

    const float* f2 = fea2 + (size_t)b * N2 * C2;
    const float* p0 = f2 + (size_t)i0 * C2;
    const float* p1 = f2 + (size_t)i1 * C2;
    const float* p2 = f2 + (size_t)i2 * C2;
    __nv_bfloat16* oh = g_interp_hi + (size_t)row * C2;
    __nv_bfloat16* ol = g_interp_lo + (size_t)row * C2;

    #pragma unroll
    for (int c = lane; c < C2; c += 32) {
        float v = w0 * p0[c] + w1 * p1[c] + w2 * p2[c];
        __nv_bfloat16 h, l;
        split_bf16(v, h, l);
        oh[c] = h;
        ol[c] = l;
    }
}

// ---------------------------------------------------------------------------
// Kernels 2/3: bf16 mma.sync GEMM with 3-term hi/lo split (fp32-accurate).
//   out[M,256] = ReLU(A[M,K] @ W[K,256] + bias)
// CTA tile 128x128, BK=64 bf16.  8 warps (2m x 4n), warp tile 64x32.
// SMEM rows: 64 bf16 = 128B data padded to 144B stride -> conflict-free
// ldmatrix without swizzle.  Double-buffered cp.async pipeline.
// ---------------------------------------------------------------------------
#define ROW_B     144                       // padded row stride (bytes)
#define ARR_B     (128 * ROW_B)             // 18432 per operand array
#define STAGE_B   (4 * ARR_B)               // A_hi, A_lo, B_hi, B_lo
#define SM_TOTAL  (2 * STAGE_B)             // 147456 bytes
#define OFF_A_HI  0
#define OFF_A_LO  ARR_B
#define OFF_B_HI  (2 * ARR_B)
#define OFF_B_LO  (3 * ARR_B)

template <int K_TOT, bool CONCAT, bool SPLIT_OUT>
__global__ __launch_bounds__(256, 1)
void gemm_bf16x3_kernel(const __nv_bfloat16* __restrict__ A0h,  // fea1/hidden hi
                        const __nv_bfloat16* __restrict__ A0l,
                        const __nv_bfloat16* __restrict__ A1h,  // interp hi (CONCAT)
                        const __nv_bfloat16* __restrict__ A1l,
                        const __nv_bfloat16* __restrict__ Wth,  // [256][K_TOT]
                        const __nv_bfloat16* __restrict__ Wtl,
                        const float* __restrict__ bias,
                        float* __restrict__ out_f32,            // !SPLIT_OUT
                        __nv_bfloat16* __restrict__ out_hi,     // SPLIT_OUT
                        __nv_bfloat16* __restrict__ out_lo)
{
    extern __shared__ char smem[];
    const uint32_t smem_u32 = smem_to_u32(smem);
    const int tid  = threadIdx.x;
    const int wid  = tid >> 5;
    const int lane = tid & 31;
    const int wm   = wid >> 2;          // 0..1 (m)
    const int wn   = wid & 3;           // 0..3 (n)

    const int rowBase = blockIdx.y * 128;
    const int colBase = blockIdx.x * 128;

    constexpr int NT = K_TOT / 64;

    // per-thread cp.async coordinates: chunk c = tid + j*256, r=c>>3, kg=c&7
    const int cp_r  = tid >> 3;          // base row (j adds 32)
    const int cp_kg = tid & 7;           // 16B group within row

    // issue one stage of cp.async (A hi/lo + B hi/lo)
    auto issue_stage = [&](int ci) {
        const uint32_t st = smem_u32 + (uint32_t)(ci & 1) * STAGE_B;
        const int kt = ci * 64;
        #pragma unroll
        for (int j = 0; j < 4; j++) {
            const int r  = cp_r + j * 32;
            const uint32_t doff = (uint32_t)(r * ROW_B + cp_kg * 16);
            // ---- A ----
            const __nv_bfloat16 *sh, *sl;
            if (CONCAT) {
                if (kt < C1) {
                    sh = A0h + (size_t)(rowBase + r) * C1 + kt + cp_kg * 8;
                    sl = A0l + (size_t)(rowBase + r) * C1 + kt + cp_kg * 8;
                } else {
                    sh = A1h + (size_t)(rowBase + r) * C2 + (kt - C1) + cp_kg * 8;
                    sl = A1l + (size_t)(rowBase + r) * C2 + (kt - C1) + cp_kg * 8;
                }
            } else {
                sh = A0h + (size_t)(rowBase + r) * K_TOT + kt + cp_kg * 8;
                sl = A0l + (size_t)(rowBase + r) * K_TOT + kt + cp_kg * 8;
            }
            cp_async16(st + OFF_A_HI + doff, sh);
            cp_async16(st + OFF_A_LO + doff, sl);
            // ---- B ----
            const __nv_bfloat16* bh = Wth + (size_t)(colBase + r) * K_TOT + kt + cp_kg * 8;
            const __nv_bfloat16* bl = Wtl + (size_t)(colBase + r) * K_TOT + kt + cp_kg * 8;
            cp_async16(st + OFF_B_HI + doff, bh);
            cp_async16(st + OFF_B_LO + doff, bl);
        }
    };

    // ldmatrix per-lane address components
    const int a_row  = wm * 64 + (lane & 7) + ((lane >> 3) & 1) * 8;
    const int a_kln  = ((lane >> 4) & 1) * 8;                 // +8 k for mats 2,3
    const uint32_t a_base = (uint32_t)(a_row * ROW_B + a_kln * 2);
    const int l2     = lane & 15;
    const int b_row  = wn * 32 + (l2 & 7);
    const int b_kln  = ((l2 >> 3) & 1) * 8;
    const uint32_t b_base = (uint32_t)(b_row * ROW_B + b_kln * 2);

    float acc[4][4][4];
    #pragma unroll
    for (int i = 0; i < 4; i++)
        #pragma unroll
        for (int j = 0; j < 4; j++)
            #pragma unroll
            for (int k = 0; k < 4; k++) acc[i][j][k] = 0.0f;

    issue_stage(0);
    CP_COMMIT();

    for (int ci = 0; ci < NT; ci++) {
        if (ci + 1 < NT) { issue_stage(ci + 1); CP_COMMIT(); }
        if (ci + 1 < NT) { CP_WAIT(1); } else { CP_WAIT(0); }
        __syncthreads();

        const uint32_t st = smem_u32 + (uint32_t)(ci & 1) * STAGE_B;
        const uint32_t aH = st + OFF_A_HI + a_base;
        const uint32_t aL = st + OFF_A_LO + a_base;
        const uint32_t bH = st + OFF_B_HI + b_base;
        const uint32_t bL = st + OFF_B_LO + b_base;

        #pragma unroll
        for (int ks = 0; ks < 4; ks++) {
            uint32_t ah[4][4], al[4][4], bh[4][2], bl[4][2];
            #pragma unroll
            for (int mt = 0; mt < 4; mt++) {
                ldsm_x4(ah[mt][0], ah[mt][1], ah[mt][2], ah[mt][3],
                        aH + mt * (16 * ROW_B) + ks * 32);
                ldsm_x4(al[mt][0], al[mt][1], al[mt][2], al[mt][3],
                        aL + mt * (16 * ROW_B) + ks * 32);
            }
            #pragma unroll
            for (int nt = 0; nt < 4; nt++) {
                ldsm_x2(bh[nt][0], bh[nt][1], bH + nt * (8 * ROW_B) + ks * 32);
                ldsm_x2(bl[nt][0], bl[nt][1], bL + nt * (8 * ROW_B) + ks * 32);
            }
            #pragma unroll
            for (int mt = 0; mt < 4; mt++)
                #pragma unroll
                for (int nt = 0; nt < 4; nt++) {
                    mma_bf16(acc[mt][nt], ah[mt], bh[nt]);
                    mma_bf16(acc[mt][nt], ah[mt], bl[nt]);
                    mma_bf16(acc[mt][nt], al[mt], bh[nt]);
                }
        }
        __syncthreads();
    }

    // Epilogue: bias + ReLU, write fp32 or bf16 hi/lo split
    const int er = rowBase + wm * 64 + (lane >> 2);        // + mt*16 (+8)
    const int ec = colBase + wn * 32 + (lane & 3) * 2;     // + nt*8 (+1)
    #pragma unroll
    for (int mt = 0; mt < 4; mt++) {
        #pragma unroll
        for (int nt = 0; nt < 4; nt++) {
            const int c0 = ec + nt * 8;
            const float bi0 = bias[c0], bi1 = bias[c0 + 1];
            const int r0 = er + mt * 16;
            float v00 = fmaxf(acc[mt][nt][0] + bi0, 0.0f);
            float v01 = fmaxf(acc[mt][nt][1] + bi1, 0.0f);
            float v10 = fmaxf(acc[mt][nt][2] + bi0, 0.0f);
            float v11 = fmaxf(acc[mt][nt][3] + bi1, 0.0f);
            if (SPLIT_OUT) {
                __nv_bfloat16 h0, l0, h1, l1;
                split_bf16(v00, h0, l0); split_bf16(v01, h1, l1);
                *(__nv_bfloat162*)(out_hi + (size_t)r0 * 256 + c0) = __nv_bfloat162(h0, h1);
                *(__nv_bfloat162*)(out_lo + (size_t)r0 * 256 + c0) = __nv_bfloat162(l0, l1);
                split_bf16(v10, h0, l0); split_bf16(v11, h1, l1);
                *(__nv_bfloat162*)(out_hi + (size_t)(r0 + 8) * 256 + c0) = __nv_bfloat162(h0, h1);
                *(__nv_bfloat162*)(out_lo + (size_t)(r0 + 8) * 256 + c0) = __nv_bfloat162(l0, l1);
            } else {
                *(float2*)(out_f32 + (size_t)r0 * 256 + c0)       = make_float2(v00, v01);
                *(float2*)(out_f32 + (size_t)(r0 + 8) * 256 + c0) = make_float2(v10, v11);
            }
        }
    }
}

// ---------------------------------------------------------------------------
extern "C" void kernel_launch(void* const* d_in, const int* in_sizes, int n_in,
                              void* d_out, int out_size)
{
    const float* xyz1 = (const float*)d_in[0];   // [16,4096,3]
    const float* xyz2 = (const float*)d_in[1];   // [16,1024,3]
    const float* fea1 = (const float*)d_in[2];   // [16,4096,128]
    const float* fea2 = (const float*)d_in[3];   // [16,1024,256]
    const float* W1   = (const float*)d_in[4];   // [384,256]
    const float* b1   = (const float*)d_in[5];   // [256]
    const float* W2   = (const float*)d_in[6];   // [256,256]
    const float* b2   = (const float*)d_in[7];   // [256]
    float* out        = (float*)d_out;           // [16,4096,256]

    __nv_bfloat16 *f1h, *f1l, *ith, *itl, *hdh, *hdl, *w1h, *w1l, *w2h, *w2l;
    cudaGetSymbolAddress((void**)&f1h, g_fea1_hi);
    cudaGetSymbolAddress((void**)&f1l, g_fea1_lo);
    cudaGetSymbolAddress((void**)&ith, g_interp_hi);
    cudaGetSymbolAddress((void**)&itl, g_interp_lo);
    cudaGetSymbolAddress((void**)&hdh, g_hidden_hi);
    cudaGetSymbolAddress((void**)&hdl, g_hidden_lo);
    cudaGetSymbolAddress((void**)&w1h, g_w1t_hi);
    cudaGetSymbolAddress((void**)&w1l, g_w1t_lo);
    cudaGetSymbolAddress((void**)&w2h, g_w2t_hi);
    cudaGetSymbolAddress((void**)&w2l, g_w2t_lo);

    cudaFuncSetAttribute(gemm_bf16x3_kernel<CIN, true, true>,
                         cudaFuncAttributeMaxDynamicSharedMemorySize, SM_TOTAL);
    cudaFuncSetAttribute(gemm_bf16x3_kernel<CH, false, false>,
                         cudaFuncAttributeMaxDynamicSharedMemorySize, SM_TOTAL);

    // 0) operand preparation (small)
    wsplit_kernel<<<CIN, 256>>>(W1, w1h, w1l, CIN);
    wsplit_kernel<<<CH,  256>>>(W2, w2h, w2l, CH);
    asplit_kernel<<<(MTOT * C1) / 1024, 256>>>(fea1, f1h, f1l);

    // 1) 3-NN + interpolation -> interp hi/lo
    knn_interp_kernel<<<MTOT / 8, 256>>>(xyz1, xyz2, fea2);

    // 2) hidden = ReLU([fea1|interp] @ W1 + b1)  -> bf16 hi/lo
    {
        dim3 grid(2, MTOT / 128);
        gemm_bf16x3_kernel<CIN, true, true><<<grid, 256, SM_TOTAL>>>(
            f1h, f1l, ith, itl, w1h, w1l, b1, nullptr, hdh, hdl);
    }

    // 3) out = ReLU(hidden @ W2 + b2)  -> fp32
    {
        dim3 grid(2, MTOT / 128);
        gemm_bf16x3_kernel<CH, false, false><<<grid, 256, SM_TOTAL>>>(
            hdh, hdl, nullptr, nullptr, w2h, w2l, b2, out, nullptr, nullptr);
    }
}

// round 4
// speedup vs baseline: 3.2752x; 1.0631x over previous
#include <cuda_runtime.h>
#include <cuda_bf16.h>
#include <cstdint>

// Problem constants (fixed by setup_inputs)
#define BSZ   16
#define N1    4096
#define N2    1024
#define C1    128
#define C2    256
#define CIN   384
#define CH    256
#define MTOT  (BSZ * N1)   // 65536 rows

// ---------------------------------------------------------------------------
// Scratch (static __device__ — allocation-free per harness rules)
// ---------------------------------------------------------------------------
__device__ __align__(16) __nv_bfloat16 g_fea1_hi[MTOT * C1];
__device__ __align__(16) __nv_bfloat16 g_fea1_lo[MTOT * C1];
__device__ __align__(16) __nv_bfloat16 g_interp_hi[MTOT * C2];
__device__ __align__(16) __nv_bfloat16 g_interp_lo[MTOT * C2];
__device__ __align__(16) __nv_bfloat16 g_hidden_hi[MTOT * CH];
__device__ __align__(16) __nv_bfloat16 g_hidden_lo[MTOT * CH];
__device__ __align__(16) __nv_bfloat16 g_w1t_hi[256 * CIN];   // W1^T [N][K]
__device__ __align__(16) __nv_bfloat16 g_w1t_lo[256 * CIN];
__device__ __align__(16) __nv_bfloat16 g_w2t_hi[256 * CH];
__device__ __align__(16) __nv_bfloat16 g_w2t_lo[256 * CH];

// ---------------------------------------------------------------------------
// PTX helpers (sm_80-era only — valid at compute_100 without 'a' suffix)
// ---------------------------------------------------------------------------
__device__ __forceinline__ uint32_t smem_to_u32(const void* p) {
    uint32_t a;
    asm("{ .reg .u64 t; cvta.to.shared.u64 t, %1; cvt.u32.u64 %0, t; }"
        : "=r"(a) : "l"(p));
    return a;
}

__device__ __forceinline__ void cp_async16(uint32_t dst_smem, const void* src) {
    asm volatile("cp.async.cg.shared.global [%0], [%1], 16;"
                 :: "r"(dst_smem), "l"(src));
}
#define CP_COMMIT()  asm volatile("cp.async.commit_group;")
#define CP_WAIT(n)   asm volatile("cp.async.wait_group %0;" :: "n"(n))

__device__ __forceinline__ void ldsm_x4(uint32_t& r0, uint32_t& r1,
                                        uint32_t& r2, uint32_t& r3, uint32_t addr) {
    asm volatile("ldmatrix.sync.aligned.m8n8.x4.shared.b16 {%0,%1,%2,%3}, [%4];"
                 : "=r"(r0), "=r"(r1), "=r"(r2), "=r"(r3) : "r"(addr));
}
__device__ __forceinline__ void ldsm_x2(uint32_t& r0, uint32_t& r1, uint32_t addr) {
    asm volatile("ldmatrix.sync.aligned.m8n8.x2.shared.b16 {%0,%1}, [%2];"
                 : "=r"(r0), "=r"(r1) : "r"(addr));
}

__device__ __forceinline__ void mma_bf16(float* c, const uint32_t* a, const uint32_t* b) {
    asm volatile(
        "mma.sync.aligned.m16n8k16.row.col.f32.bf16.bf16.f32 "
        "{%0,%1,%2,%3}, {%4,%5,%6,%7}, {%8,%9}, {%0,%1,%2,%3};"
        : "+f"(c[0]), "+f"(c[1]), "+f"(c[2]), "+f"(c[3])
        : "r"(a[0]), "r"(a[1]), "r"(a[2]), "r"(a[3]), "r"(b[0]), "r"(b[1]));
}

__device__ __forceinline__ void split_bf16(float v, __nv_bfloat16& h, __nv_bfloat16& l) {
    h = __float2bfloat16_rn(v);
    l = __float2bfloat16_rn(v - __bfloat162float(h));
}

// ---------------------------------------------------------------------------
// Fat kernel 1: knn+interp  |  fea1 split  |  W1 split  |  W2 split
// (memory-bound split blocks co-schedule with alu-bound knn blocks)
// Grid ranges:
//   [0, 8192)           knn (8 warps/block, one batch tile each)
//   [8192, 10240)       fea1 fp32 -> bf16 hi/lo (4 float4 / thread)
//   [10240, 10624)      W1 transpose+split (row k = blk-10240)
//   [10624, 10880)      W2 transpose+split
// ---------------------------------------------------------------------------
#define KNN_BLOCKS   8192
#define ASPLIT_BLOCKS 2048
#define GRID_TOTAL   (KNN_BLOCKS + ASPLIT_BLOCKS + CIN + CH)

__global__ __launch_bounds__(256)
void prep_knn_kernel(const float* __restrict__ xyz1,
                     const float* __restrict__ xyz2,
                     const float* __restrict__ fea1,
                     const float* __restrict__ fea2,
                     const float* __restrict__ W1,
                     const float* __restrict__ W2)
{
    const int blk = blockIdx.x;
    const int tid = threadIdx.x;

    // ---------------- fea1 split branch ----------------
    if (blk >= KNN_BLOCKS) {
        if (blk < KNN_BLOCKS + ASPLIT_BLOCKS) {
            const size_t base = ((size_t)(blk - KNN_BLOCKS) * 256 + tid) * 4;
            #pragma unroll
            for (int k = 0; k < 4; k++) {
                const size_t i4 = base + k;
                float4 v = *(const float4*)(fea1 + i4 * 4);
                __nv_bfloat16 h0, l0, h1, l1, h2, l2, h3, l3;
                split_bf16(v.x, h0, l0); split_bf16(v.y, h1, l1);
                split_bf16(v.z, h2, l2); split_bf16(v.w, h3, l3);
                *(__nv_bfloat162*)(g_fea1_hi + i4 * 4)     = __nv_bfloat162(h0, h1);
                *(__nv_bfloat162*)(g_fea1_hi + i4 * 4 + 2) = __nv_bfloat162(h2, h3);
                *(__nv_bfloat162*)(g_fea1_lo + i4 * 4)     = __nv_bfloat162(l0, l1);
                *(__nv_bfloat162*)(g_fea1_lo + i4 * 4 + 2) = __nv_bfloat162(l2, l3);
            }
        } else if (blk < KNN_BLOCKS + ASPLIT_BLOCKS + CIN) {
            const int k = blk - (KNN_BLOCKS + ASPLIT_BLOCKS);
            float w = W1[(size_t)k * 256 + tid];
            __nv_bfloat16 h, l;
            split_bf16(w, h, l);
            g_w1t_hi[(size_t)tid * CIN + k] = h;
            g_w1t_lo[(size_t)tid * CIN + k] = l;
        } else {
            const int k = blk - (KNN_BLOCKS + ASPLIT_BLOCKS + CIN);
            float w = W2[(size_t)k * 256 + tid];
            __nv_bfloat16 h, l;
            split_bf16(w, h, l);
            g_w2t_hi[(size_t)tid * CH + k] = h;
            g_w2t_lo[(size_t)tid * CH + k] = l;
        }
        return;
    }

    // ---------------- knn branch ----------------
    __shared__ float4 sc[N2];    // (x, y, z, |p|^2)

    const int b       = blk >> 9;
    const int pt_base = (blk & 511) * 8;

    const float* x2 = xyz2 + (size_t)b * N2 * 3;
    for (int i = tid; i < N2; i += 256) {
        float px = x2[i * 3 + 0];
        float py = x2[i * 3 + 1];
        float pz = x2[i * 3 + 2];
        sc[i] = make_float4(px, py, pz, px * px + py * py + pz * pz);
    }
    __syncthreads();

    const int warp = tid >> 5;
    const int lane = tid & 31;
    const int row  = b * N1 + pt_base + warp;

    const float* q = xyz1 + (size_t)row * 3;
    const float qx = q[0], qy = q[1], qz = q[2];
    const float qq   = qx * qx + qy * qy + qz * qz;
    const float m2qx = -2.0f * qx, m2qy = -2.0f * qy, m2qz = -2.0f * qz;

    float d0 = 1e30f, d1 = 1e30f, d2 = 1e30f;
    int   i0 = 0,     i1 = 0,     i2 = 0;

    #pragma unroll 4
    for (int j = lane; j < N2; j += 32) {
        const float4 c = sc[j];
        // d = qq + pp - 2*q.p   (fp32, same quantities as reference)
        float d = fmaf(c.x, m2qx, fmaf(c.y, m2qy, fmaf(c.z, m2qz, qq + c.w)));
        if (d < d2) {
            if (d < d1) {
                d2 = d1; i2 = i1;
                if (d < d0) { d1 = d0; i1 = i0; d0 = d; i0 = j; }
                else        { d1 = d;  i1 = j; }
            } else { d2 = d; i2 = j; }
        }
    }

    #pragma unroll
    for (int off = 16; off; off >>= 1) {
        float e[3]; int ei[3];
        e[0]  = __shfl_xor_sync(0xffffffffu, d0, off);
        e[1]  = __shfl_xor_sync(0xffffffffu, d1, off);
        e[2]  = __shfl_xor_sync(0xffffffffu, d2, off);
        ei[0] = __shfl_xor_sync(0xffffffffu, i0, off);
        ei[1] = __shfl_xor_sync(0xffffffffu, i1, off);
        ei[2] = __shfl_xor_sync(0xffffffffu, i2, off);
        #pragma unroll
        for (int k = 0; k < 3; k++) {
            float d = e[k]; int idx = ei[k];
            if (d < d2) {
                if (d < d1) {
                    d2 = d1; i2 = i1;
                    if (d < d0) { d1 = d0; i1 = i0; d0 = d; i0 = idx; }
                    else        { d1 = d;  i1 = idx; }
                } else { d2 = d; i2 = idx; }
            }
        }
    }

    const float r0 = 1.0f / (d0 + 1e-8f);
    const float r1 = 1.0f / (d1 + 1e-8f);
    const float r2 = 1.0f / (d2 + 1e-8f);
    const float inv_s = 1.0f / (r0 + r1 + r2);
    const float w0 = r0 * inv_s, w1 = r1 * inv_s, w2 = r2 * inv_s;

    const float* f2 = fea2 + (size_t)b * N2 * C2;
    const float* p0 = f2 + (size_t)i0 * C2;
    const float* p1 = f2 + (size_t)i1 * C2;
    const float* p2 = f2 + (size_t)i2 * C2;
    __nv_bfloat16* oh = g_interp_hi + (size_t)row * C2;
    __nv_bfloat16* ol = g_interp_lo + (size_t)row * C2;

    #pragma unroll
    for (int c = lane; c < C2; c += 32) {
        float v = w0 * p0[c] + w1 * p1[c] + w2 * p2[c];
        __nv_bfloat16 h, l;
        split_bf16(v, h, l);
        oh[c] = h;
        ol[c] = l;
    }
}

// ---------------------------------------------------------------------------
// Kernels 2/3: bf16 mma.sync GEMM with 3-term hi/lo split (fp32-accurate).
//   out[M,256] = ReLU(A[M,K] @ W[K,256] + bias)
// CTA 128x128, BK=64 bf16.  8 warps (2m x 4n), warp tile 64x32.
// 144B padded rows (conflict-free ldmatrix).  3-stage cp.async pipeline.
// ---------------------------------------------------------------------------
#define ROW_B     144
#define ARR_B     (128 * ROW_B)             // 18432
#define STAGE_B   (4 * ARR_B)               // 73728
#define SM_TOTAL  (3 * STAGE_B)             // 221184
#define OFF_A_HI  0
#define OFF_A_LO  ARR_B
#define OFF_B_HI  (2 * ARR_B)
#define OFF_B_LO  (3 * ARR_B)

template <int K_TOT, bool CONCAT, bool SPLIT_OUT>
__global__ __launch_bounds__(256, 1)
void gemm_bf16x3_kernel(const __nv_bfloat16* __restrict__ A0h,
                        const __nv_bfloat16* __restrict__ A0l,
                        const __nv_bfloat16* __restrict__ A1h,
                        const __nv_bfloat16* __restrict__ A1l,
                        const __nv_bfloat16* __restrict__ Wth,
                        const __nv_bfloat16* __restrict__ Wtl,
                        const float* __restrict__ bias,
                        float* __restrict__ out_f32,
                        __nv_bfloat16* __restrict__ out_hi,
                        __nv_bfloat16* __restrict__ out_lo)
{
    extern __shared__ char smem[];
    const uint32_t smem_u32 = smem_to_u32(smem);
    const int tid  = threadIdx.x;
    const int wid  = tid >> 5;
    const int lane = tid & 31;
    const int wm   = wid >> 2;
    const int wn   = wid & 3;

    const int rowBase = blockIdx.y * 128;
    const int colBase = blockIdx.x * 128;

    constexpr int NT = K_TOT / 64;

    const int cp_r  = tid >> 3;
    const int cp_kg = tid & 7;

    auto issue_stage = [&](int ci) {
        const uint32_t st = smem_u32 + (uint32_t)(ci % 3) * STAGE_B;
        const int kt = ci * 64;
        #pragma unroll
        for (int j = 0; j < 4; j++) {
            const int r  = cp_r + j * 32;
            const uint32_t doff = (uint32_t)(r * ROW_B + cp_kg * 16);
            const __nv_bfloat16 *sh, *sl;
            if (CONCAT) {
                if (kt < C1) {
                    sh = A0h + (size_t)(rowBase + r) * C1 + kt + cp_kg * 8;
                    sl = A0l + (size_t)(rowBase + r) * C1 + kt + cp_kg * 8;
                } else {
                    sh = A1h + (size_t)(rowBase + r) * C2 + (kt - C1) + cp_kg * 8;
                    sl = A1l + (size_t)(rowBase + r) * C2 + (kt - C1) + cp_kg * 8;
                }
            } else {
                sh = A0h + (size_t)(rowBase + r) * K_TOT + kt + cp_kg * 8;
                sl = A0l + (size_t)(rowBase + r) * K_TOT + kt + cp_kg * 8;
            }
            cp_async16(st + OFF_A_HI + doff, sh);
            cp_async16(st + OFF_A_LO + doff, sl);
            const __nv_bfloat16* bh = Wth + (size_t)(colBase + r) * K_TOT + kt + cp_kg * 8;
            const __nv_bfloat16* bl = Wtl + (size_t)(colBase + r) * K_TOT + kt + cp_kg * 8;
            cp_async16(st + OFF_B_HI + doff, bh);
            cp_async16(st + OFF_B_LO + doff, bl);
        }
    };

    const int a_row  = wm * 64 + (lane & 7) + ((lane >> 3) & 1) * 8;
    const int a_kln  = ((lane >> 4) & 1) * 8;
    const uint32_t a_base = (uint32_t)(a_row * ROW_B + a_kln * 2);
    const int l2     = lane & 15;
    const int b_row  = wn * 32 + (l2 & 7);
    const int b_kln  = ((l2 >> 3) & 1) * 8;
    const uint32_t b_base = (uint32_t)(b_row * ROW_B + b_kln * 2);

    float acc[4][4][4];
    #pragma unroll
    for (int i = 0; i < 4; i++)
        #pragma unroll
        for (int j = 0; j < 4; j++)
            #pragma unroll
            for (int k = 0; k < 4; k++) acc[i][j][k] = 0.0f;

    issue_stage(0);
    CP_COMMIT();
    if (NT > 1) { issue_stage(1); CP_COMMIT(); }

    for (int ci = 0; ci < NT; ci++) {
        if (ci + 1 < NT) { CP_WAIT(1); } else { CP_WAIT(0); }
        __syncthreads();
        // Issue stage ci+2 after the barrier: its buffer (ci+2)%3 was last
        // read during compute of ci-1, which every warp finished before this
        // barrier. The copy overlaps the whole compute of chunk ci.
        if (ci + 2 < NT) { issue_stage(ci + 2); CP_COMMIT(); }

        const uint32_t st = smem_u32 + (uint32_t)(ci % 3) * STAGE_B;
        const uint32_t aH = st + OFF_A_HI + a_base;
        const uint32_t aL = st + OFF_A_LO + a_base;
        const uint32_t bH = st + OFF_B_HI + b_base;
        const uint32_t bL = st + OFF_B_LO + b_base;

        #pragma unroll
        for (int ks = 0; ks < 4; ks++) {
            uint32_t ah[4][4], al[4][4], bh[4][2], bl[4][2];
            #pragma unroll
            for (int mt = 0; mt < 4; mt++) {
                ldsm_x4(ah[mt][0], ah[mt][1], ah[mt][2], ah[mt][3],
                        aH + mt * (16 * ROW_B) + ks * 32);
                ldsm_x4(al[mt][0], al[mt][1], al[mt][2], al[mt][3],
                        aL + mt * (16 * ROW_B) + ks * 32);
            }
            #pragma unroll
            for (int nt = 0; nt < 4; nt++) {
                ldsm_x2(bh[nt][0], bh[nt][1], bH + nt * (8 * ROW_B) + ks * 32);
                ldsm_x2(bl[nt][0], bl[nt][1], bL + nt * (8 * ROW_B) + ks * 32);
            }
            #pragma unroll
            for (int mt = 0; mt < 4; mt++)
                #pragma unroll
                for (int nt = 0; nt < 4; nt++) {
                    mma_bf16(acc[mt][nt], ah[mt], bh[nt]);
                    mma_bf16(acc[mt][nt], ah[mt], bl[nt]);
                    mma_bf16(acc[mt][nt], al[mt], bh[nt]);
                }
        }
        __syncthreads();
    }

    const int er = rowBase + wm * 64 + (lane >> 2);
    const int ec = colBase + wn * 32 + (lane & 3) * 2;
    #pragma unroll
    for (int mt = 0; mt < 4; mt++) {
        #pragma unroll
        for (int nt = 0; nt < 4; nt++) {
            const int c0 = ec + nt * 8;
            const float bi0 = bias[c0], bi1 = bias[c0 + 1];
            const int r0 = er + mt * 16;
            float v00 = fmaxf(acc[mt][nt][0] + bi0, 0.0f);
            float v01 = fmaxf(acc[mt][nt][1] + bi1, 0.0f);
            float v10 = fmaxf(acc[mt][nt][2] + bi0, 0.0f);
            float v11 = fmaxf(acc[mt][nt][3] + bi1, 0.0f);
            if (SPLIT_OUT) {
                __nv_bfloat16 h0, l0, h1, l1;
                split_bf16(v00, h0, l0); split_bf16(v01, h1, l1);
                *(__nv_bfloat162*)(out_hi + (size_t)r0 * 256 + c0) = __nv_bfloat162(h0, h1);
                *(__nv_bfloat162*)(out_lo + (size_t)r0 * 256 + c0) = __nv_bfloat162(l0, l1);
                split_bf16(v10, h0, l0); split_bf16(v11, h1, l1);
                *(__nv_bfloat162*)(out_hi + (size_t)(r0 + 8) * 256 + c0) = __nv_bfloat162(h0, h1);
                *(__nv_bfloat162*)(out_lo + (size_t)(r0 + 8) * 256 + c0) = __nv_bfloat162(l0, l1);
            } else {
                *(float2*)(out_f32 + (size_t)r0 * 256 + c0)       = make_float2(v00, v01);
                *(float2*)(out_f32 + (size_t)(r0 + 8) * 256 + c0) = make_float2(v10, v11);
            }
        }
    }
}

// ---------------------------------------------------------------------------
extern "C" void kernel_launch(void* const* d_in, const int* in_sizes, int n_in,
                              void* d_out, int out_size)
{
    const float* xyz1 = (const float*)d_in[0];
    const float* xyz2 = (const float*)d_in[1];
    const float* fea1 = (const float*)d_in[2];
    const float* fea2 = (const float*)d_in[3];
    const float* W1   = (const float*)d_in[4];
    const float* b1   = (const float*)d_in[5];
    const float* W2   = (const float*)d_in[6];
    const float* b2   = (const float*)d_in[7];
    float* out        = (float*)d_out;

    __nv_bfloat16 *f1h, *f1l, *ith, *itl, *hdh, *hdl, *w1h, *w1l, *w2h, *w2l;
    cudaGetSymbolAddress((void**)&f1h, g_fea1_hi);
    cudaGetSymbolAddress((void**)&f1l, g_fea1_lo);
    cudaGetSymbolAddress((void**)&ith, g_interp_hi);
    cudaGetSymbolAddress((void**)&itl, g_interp_lo);
    cudaGetSymbolAddress((void**)&hdh, g_hidden_hi);
    cudaGetSymbolAddress((void**)&hdl, g_hidden_lo);
    cudaGetSymbolAddress((void**)&w1h, g_w1t_hi);
    cudaGetSymbolAddress((void**)&w1l, g_w1t_lo);
    cudaGetSymbolAddress((void**)&w2h, g_w2t_hi);
    cudaGetSymbolAddress((void**)&w2l, g_w2t_lo);

    cudaFuncSetAttribute(gemm_bf16x3_kernel<CIN, true, true>,
                         cudaFuncAttributeMaxDynamicSharedMemorySize, SM_TOTAL);
    cudaFuncSetAttribute(gemm_bf16x3_kernel<CH, false, false>,
                         cudaFuncAttributeMaxDynamicSharedMemorySize, SM_TOTAL);

    // 1) fused: knn+interp | fea1 split | W1/W2 splits
    prep_knn_kernel<<<GRID_TOTAL, 256>>>(xyz1, xyz2, fea1, fea2, W1, W2);

    // 2) hidden = ReLU([fea1|interp] @ W1 + b1) -> bf16 hi/lo
    {
        dim3 grid(2, MTOT / 128);
        gemm_bf16x3_kernel<CIN, true, true><<<grid, 256, SM_TOTAL>>>(
            f1h, f1l, ith, itl, w1h, w1l, b1, nullptr, hdh, hdl);
    }

    // 3) out = ReLU(hidden @ W2 + b2) -> fp32
    {
        dim3 grid(2, MTOT / 128);
        gemm_bf16x3_kernel<CH, false, false><<<grid, 256, SM_TOTAL>>>(
            hdh, hdl, nullptr, nullptr, w2h, w2l, b2, out, nullptr, nullptr);
    }
}

// round 5
// speedup vs baseline: 3.2982x; 1.0070x over previous
#include <cuda_runtime.h>
#include <cuda_bf16.h>
#include <cstdint>

// Problem constants (fixed by setup_inputs)
#define BSZ   16
#define N1    4096
#define N2    1024
#define C1    128
#define C2    256
#define CIN   384
#define CH    256
#define MTOT  (BSZ * N1)   // 65536 rows

// ---------------------------------------------------------------------------
// Scratch (static __device__ — allocation-free per harness rules)
// ---------------------------------------------------------------------------
__device__ __align__(16) __nv_bfloat16 g_fea1_hi[MTOT * C1];
__device__ __align__(16) __nv_bfloat16 g_fea1_lo[MTOT * C1];
__device__ __align__(16) __nv_bfloat16 g_interp_hi[MTOT * C2];
__device__ __align__(16) __nv_bfloat16 g_interp_lo[MTOT * C2];
__device__ __align__(16) __nv_bfloat16 g_hidden_hi[MTOT * CH];
__device__ __align__(16) __nv_bfloat16 g_hidden_lo[MTOT * CH];
__device__ __align__(16) __nv_bfloat16 g_w1t_hi[256 * CIN];   // W1^T [N][K]
__device__ __align__(16) __nv_bfloat16 g_w1t_lo[256 * CIN];
__device__ __align__(16) __nv_bfloat16 g_w2t_hi[256 * CH];
__device__ __align__(16) __nv_bfloat16 g_w2t_lo[256 * CH];

// ---------------------------------------------------------------------------
// PTX helpers (sm_80-era only — valid at compute_100 without 'a' suffix)
// ---------------------------------------------------------------------------
__device__ __forceinline__ uint32_t smem_to_u32(const void* p) {
    uint32_t a;
    asm("{ .reg .u64 t; cvta.to.shared.u64 t, %1; cvt.u32.u64 %0, t; }"
        : "=r"(a) : "l"(p));
    return a;
}

__device__ __forceinline__ void cp_async16(uint32_t dst_smem, const void* src) {
    asm volatile("cp.async.cg.shared.global [%0], [%1], 16;"
                 :: "r"(dst_smem), "l"(src));
}
#define CP_COMMIT()  asm volatile("cp.async.commit_group;")
#define CP_WAIT(n)   asm volatile("cp.async.wait_group %0;" :: "n"(n))

__device__ __forceinline__ void ldsm_x4(uint32_t& r0, uint32_t& r1,
                                        uint32_t& r2, uint32_t& r3, uint32_t addr) {
    asm volatile("ldmatrix.sync.aligned.m8n8.x4.shared.b16 {%0,%1,%2,%3}, [%4];"
                 : "=r"(r0), "=r"(r1), "=r"(r2), "=r"(r3) : "r"(addr));
}
__device__ __forceinline__ void ldsm_x2(uint32_t& r0, uint32_t& r1, uint32_t addr) {
    asm volatile("ldmatrix.sync.aligned.m8n8.x2.shared.b16 {%0,%1}, [%2];"
                 : "=r"(r0), "=r"(r1) : "r"(addr));
}

__device__ __forceinline__ void mma_bf16(float* c, const uint32_t* a, const uint32_t* b) {
    asm volatile(
        "mma.sync.aligned.m16n8k16.row.col.f32.bf16.bf16.f32 "
        "{%0,%1,%2,%3}, {%4,%5,%6,%7}, {%8,%9}, {%0,%1,%2,%3};"
        : "+f"(c[0]), "+f"(c[1]), "+f"(c[2]), "+f"(c[3])
        : "r"(a[0]), "r"(a[1]), "r"(a[2]), "r"(a[3]), "r"(b[0]), "r"(b[1]));
}

__device__ __forceinline__ void split_bf16(float v, __nv_bfloat16& h, __nv_bfloat16& l) {
    h = __float2bfloat16_rn(v);
    l = __float2bfloat16_rn(v - __bfloat162float(h));
}

// ---------------------------------------------------------------------------
// Fat kernel 1: knn+interp  |  fea1 split  |  W1 split  |  W2 split
// knn uses thread-per-query (broadcast candidate reads) for the search and
// warp-per-query (coalesced) for the feature gather, linked through smem.
// Grid ranges:
//   [0, 256)        knn: 256 queries/block (one thread each)
//   [256, 2304)     fea1 fp32 -> bf16 hi/lo (4 float4 / thread)
//   [2304, 2688)    W1 transpose+split
//   [2688, 2944)    W2 transpose+split
// ---------------------------------------------------------------------------
#define KNN_BLOCKS    (MTOT / 256)      // 256
#define ASPLIT_BLOCKS 2048
#define GRID_TOTAL    (KNN_BLOCKS + ASPLIT_BLOCKS + CIN + CH)

__global__ __launch_bounds__(256)
void prep_knn_kernel(const float* __restrict__ xyz1,
                     const float* __restrict__ xyz2,
                     const float* __restrict__ fea1,
                     const float* __restrict__ fea2,
                     const float* __restrict__ W1,
                     const float* __restrict__ W2)
{
    const int blk = blockIdx.x;
    const int tid = threadIdx.x;

    // ---------------- split branches ----------------
    if (blk >= KNN_BLOCKS) {
        if (blk < KNN_BLOCKS + ASPLIT_BLOCKS) {
            const size_t base = ((size_t)(blk - KNN_BLOCKS) * 256 + tid) * 4;
            #pragma unroll
            for (int k = 0; k < 4; k++) {
                const size_t i4 = base + k;
                float4 v = *(const float4*)(fea1 + i4 * 4);
                __nv_bfloat16 h0, l0, h1, l1, h2, l2, h3, l3;
                split_bf16(v.x, h0, l0); split_bf16(v.y, h1, l1);
                split_bf16(v.z, h2, l2); split_bf16(v.w, h3, l3);
                *(__nv_bfloat162*)(g_fea1_hi + i4 * 4)     = __nv_bfloat162(h0, h1);
                *(__nv_bfloat162*)(g_fea1_hi + i4 * 4 + 2) = __nv_bfloat162(h2, h3);
                *(__nv_bfloat162*)(g_fea1_lo + i4 * 4)     = __nv_bfloat162(l0, l1);
                *(__nv_bfloat162*)(g_fea1_lo + i4 * 4 + 2) = __nv_bfloat162(l2, l3);
            }
        } else if (blk < KNN_BLOCKS + ASPLIT_BLOCKS + CIN) {
            const int k = blk - (KNN_BLOCKS + ASPLIT_BLOCKS);
            float w = W1[(size_t)k * 256 + tid];
            __nv_bfloat16 h, l;
            split_bf16(w, h, l);
            g_w1t_hi[(size_t)tid * CIN + k] = h;
            g_w1t_lo[(size_t)tid * CIN + k] = l;
        } else {
            const int k = blk - (KNN_BLOCKS + ASPLIT_BLOCKS + CIN);
            float w = W2[(size_t)k * 256 + tid];
            __nv_bfloat16 h, l;
            split_bf16(w, h, l);
            g_w2t_hi[(size_t)tid * CH + k] = h;
            g_w2t_lo[(size_t)tid * CH + k] = l;
        }
        return;
    }

    // ---------------- knn branch ----------------
    __shared__ float4 sc[N2];                 // (x, y, z, |p|^2)  16KB
    __shared__ float  s_w[3][256];            // weights per query
    __shared__ int    s_id[3][256];           // neighbor indices per query

    const int b     = blk >> 4;               // 16 blocks per batch
    const int qbase = (blk & 15) * 256;

    const float* x2 = xyz2 + (size_t)b * N2 * 3;
    for (int i = tid; i < N2; i += 256) {
        float px = x2[i * 3 + 0];
        float py = x2[i * 3 + 1];
        float pz = x2[i * 3 + 2];
        sc[i] = make_float4(px, py, pz, px * px + py * py + pz * pz);
    }
    __syncthreads();

    // Phase 1: thread-per-query exact top-3 (broadcast candidate reads)
    {
        const int row = b * N1 + qbase + tid;
        const float* q = xyz1 + (size_t)row * 3;
        const float qx = q[0], qy = q[1], qz = q[2];
        const float qq   = qx * qx + qy * qy + qz * qz;
        const float m2qx = -2.0f * qx, m2qy = -2.0f * qy, m2qz = -2.0f * qz;

        float d0 = 1e30f, d1 = 1e30f, d2 = 1e30f;
        int   i0 = 0,     i1 = 0,     i2 = 0;

        #pragma unroll 8
        for (int j = 0; j < N2; j++) {
            const float4 c = sc[j];   // broadcast: all lanes same address
            float d = fmaf(c.x, m2qx, fmaf(c.y, m2qy, fmaf(c.z, m2qz, qq + c.w)));
            if (d < d2) {
                if (d < d1) {
                    d2 = d1; i2 = i1;
                    if (d < d0) { d1 = d0; i1 = i0; d0 = d; i0 = j; }
                    else        { d1 = d;  i1 = j; }
                } else { d2 = d; i2 = j; }
            }
        }

        const float r0 = 1.0f / (d0 + 1e-8f);
        const float r1 = 1.0f / (d1 + 1e-8f);
        const float r2 = 1.0f / (d2 + 1e-8f);
        const float inv_s = 1.0f / (r0 + r1 + r2);
        s_w[0][tid] = r0 * inv_s;
        s_w[1][tid] = r1 * inv_s;
        s_w[2][tid] = r2 * inv_s;
        s_id[0][tid] = i0;
        s_id[1][tid] = i1;
        s_id[2][tid] = i2;
    }
    __syncthreads();

    // Phase 2: warp-per-query coalesced gather + interpolate + bf16 split
    const int warp = tid >> 5;
    const int lane = tid & 31;
    const float* f2 = fea2 + (size_t)b * N2 * C2;

    for (int qi = warp; qi < 256; qi += 8) {
        const float w0 = s_w[0][qi], w1 = s_w[1][qi], w2 = s_w[2][qi];
        const float* p0 = f2 + (size_t)s_id[0][qi] * C2;
        const float* p1 = f2 + (size_t)s_id[1][qi] * C2;
        const float* p2 = f2 + (size_t)s_id[2][qi] * C2;
        const size_t row = (size_t)(b * N1 + qbase + qi);
        __nv_bfloat16* oh = g_interp_hi + row * C2;
        __nv_bfloat16* ol = g_interp_lo + row * C2;

        #pragma unroll
        for (int c4 = lane; c4 < 64; c4 += 32) {     // 64 float4 per row
            const float4 v0 = *(const float4*)(p0 + c4 * 4);
            const float4 v1 = *(const float4*)(p1 + c4 * 4);
            const float4 v2 = *(const float4*)(p2 + c4 * 4);
            float r[4];
            r[0] = w0 * v0.x + w1 * v1.x + w2 * v2.x;
            r[1] = w0 * v0.y + w1 * v1.y + w2 * v2.y;
            r[2] = w0 * v0.z + w1 * v1.z + w2 * v2.z;
            r[3] = w0 * v0.w + w1 * v1.w + w2 * v2.w;
            __nv_bfloat16 h[4], l[4];
            split_bf16(r[0], h[0], l[0]);
            split_bf16(r[1], h[1], l[1]);
            split_bf16(r[2], h[2], l[2]);
            split_bf16(r[3], h[3], l[3]);
            *(__nv_bfloat162*)(oh + c4 * 4)     = __nv_bfloat162(h[0], h[1]);
            *(__nv_bfloat162*)(oh + c4 * 4 + 2) = __nv_bfloat162(h[2], h[3]);
            *(__nv_bfloat162*)(ol + c4 * 4)     = __nv_bfloat162(l[0], l[1]);
            *(__nv_bfloat162*)(ol + c4 * 4 + 2) = __nv_bfloat162(l[2], l[3]);
        }
    }
}

// ---------------------------------------------------------------------------
// Kernels 2/3: bf16 mma.sync GEMM with 3-term hi/lo split (fp32-accurate).
//   out[M,256] = ReLU(A[M,K] @ W[K,256] + bias)
// CTA 128x128, BK=64 bf16.  8 warps (2m x 4n), warp tile 64x32.
// 144B padded rows (conflict-free ldmatrix).  3-stage cp.async pipeline.
// ---------------------------------------------------------------------------
#define ROW_B     144
#define ARR_B     (128 * ROW_B)             // 18432
#define STAGE_B   (4 * ARR_B)               // 73728
#define SM_TOTAL  (3 * STAGE_B)             // 221184
#define OFF_A_HI  0
#define OFF_A_LO  ARR_B
#define OFF_B_HI  (2 * ARR_B)
#define OFF_B_LO  (3 * ARR_B)

template <int K_TOT, bool CONCAT, bool SPLIT_OUT>
__global__ __launch_bounds__(256, 1)
void gemm_bf16x3_kernel(const __nv_bfloat16* __restrict__ A0h,
                        const __nv_bfloat16* __restrict__ A0l,
                        const __nv_bfloat16* __restrict__ A1h,
                        const __nv_bfloat16* __restrict__ A1l,
                        const __nv_bfloat16* __restrict__ Wth,
                        const __nv_bfloat16* __restrict__ Wtl,
                        const float* __restrict__ bias,
                        float* __restrict__ out_f32,
                        __nv_bfloat16* __restrict__ out_hi,
                        __nv_bfloat16* __restrict__ out_lo)
{
    extern __shared__ char smem[];
    const uint32_t smem_u32 = smem_to_u32(smem);
    const int tid  = threadIdx.x;
    const int wid  = tid >> 5;
    const int lane = tid & 31;
    const int wm   = wid >> 2;
    const int wn   = wid & 3;

    const int rowBase = blockIdx.y * 128;
    const int colBase = blockIdx.x * 128;

    constexpr int NT = K_TOT / 64;

    const int cp_r  = tid >> 3;
    const int cp_kg = tid & 7;

    auto issue_stage = [&](int ci) {
        const uint32_t st = smem_u32 + (uint32_t)(ci % 3) * STAGE_B;
        const int kt = ci * 64;
        #pragma unroll
        for (int j = 0; j < 4; j++) {
            const int r  = cp_r + j * 32;
            const uint32_t doff = (uint32_t)(r * ROW_B + cp_kg * 16);
            const __nv_bfloat16 *sh, *sl;
            if (CONCAT) {
                if (kt < C1) {
                    sh = A0h + (size_t)(rowBase + r) * C1 + kt + cp_kg * 8;
                    sl = A0l + (size_t)(rowBase + r) * C1 + kt + cp_kg * 8;
                } else {
                    sh = A1h + (size_t)(rowBase + r) * C2 + (kt - C1) + cp_kg * 8;
                    sl = A1l + (size_t)(rowBase + r) * C2 + (kt - C1) + cp_kg * 8;
                }
            } else {
                sh = A0h + (size_t)(rowBase + r) * K_TOT + kt + cp_kg * 8;
                sl = A0l + (size_t)(rowBase + r) * K_TOT + kt + cp_kg * 8;
            }
            cp_async16(st + OFF_A_HI + doff, sh);
            cp_async16(st + OFF_A_LO + doff, sl);
            const __nv_bfloat16* bh = Wth + (size_t)(colBase + r) * K_TOT + kt + cp_kg * 8;
            const __nv_bfloat16* bl = Wtl + (size_t)(colBase + r) * K_TOT + kt + cp_kg * 8;
            cp_async16(st + OFF_B_HI + doff, bh);
            cp_async16(st + OFF_B_LO + doff, bl);
        }
    };

    const int a_row  = wm * 64 + (lane & 7) + ((lane >> 3) & 1) * 8;
    const int a_kln  = ((lane >> 4) & 1) * 8;
    const uint32_t a_base = (uint32_t)(a_row * ROW_B + a_kln * 2);
    const int l2     = lane & 15;
    const int b_row  = wn * 32 + (l2 & 7);
    const int b_kln  = ((l2 >> 3) & 1) * 8;
    const uint32_t b_base = (uint32_t)(b_row * ROW_B + b_kln * 2);

    float acc[4][4][4];
    #pragma unroll
    for (int i = 0; i < 4; i++)
        #pragma unroll
        for (int j = 0; j < 4; j++)
            #pragma unroll
            for (int k = 0; k < 4; k++) acc[i][j][k] = 0.0f;

    issue_stage(0);
    CP_COMMIT();
    if (NT > 1) { issue_stage(1); CP_COMMIT(); }

    for (int ci = 0; ci < NT; ci++) {
        if (ci + 1 < NT) { CP_WAIT(1); } else { CP_WAIT(0); }
        __syncthreads();
        // Stage ci+2 overwrites buffer (ci-1)%3; every warp has passed the
        // barrier above only after finishing compute of chunk ci-1, so the
        // overwrite is safe and no trailing barrier is needed.
        if (ci + 2 < NT) { issue_stage(ci + 2); CP_COMMIT(); }

        const uint32_t st = smem_u32 + (uint32_t)(ci % 3) * STAGE_B;
        const uint32_t aH = st + OFF_A_HI + a_base;
        const uint32_t aL = st + OFF_A_LO + a_base;
        const uint32_t bH = st + OFF_B_HI + b_base;
        const uint32_t bL = st + OFF_B_LO + b_base;

        #pragma unroll
        for (int ks = 0; ks < 4; ks++) {
            uint32_t ah[4][4], al[4][4], bh[4][2], bl[4][2];
            #pragma unroll
            for (int mt = 0; mt < 4; mt++) {
                ldsm_x4(ah[mt][0], ah[mt][1], ah[mt][2], ah[mt][3],
                        aH + mt * (16 * ROW_B) + ks * 32);
                ldsm_x4(al[mt][0], al[mt][1], al[mt][2], al[mt][3],
                        aL + mt * (16 * ROW_B) + ks * 32);
            }
            #pragma unroll
            for (int nt = 0; nt < 4; nt++) {
                ldsm_x2(bh[nt][0], bh[nt][1], bH + nt * (8 * ROW_B) + ks * 32);
                ldsm_x2(bl[nt][0], bl[nt][1], bL + nt * (8 * ROW_B) + ks * 32);
            }
            #pragma unroll
            for (int mt = 0; mt < 4; mt++)
                #pragma unroll
                for (int nt = 0; nt < 4; nt++) {
                    mma_bf16(acc[mt][nt], ah[mt], bh[nt]);
                    mma_bf16(acc[mt][nt], ah[mt], bl[nt]);
                    mma_bf16(acc[mt][nt], al[mt], bh[nt]);
                }
        }
    }

    const int er = rowBase + wm * 64 + (lane >> 2);
    const int ec = colBase + wn * 32 + (lane & 3) * 2;
    #pragma unroll
    for (int mt = 0; mt < 4; mt++) {
        #pragma unroll
        for (int nt = 0; nt < 4; nt++) {
            const int c0 = ec + nt * 8;
            const float bi0 = bias[c0], bi1 = bias[c0 + 1];
            const int r0 = er + mt * 16;
            float v00 = fmaxf(acc[mt][nt][0] + bi0, 0.0f);
            float v01 = fmaxf(acc[mt][nt][1] + bi1, 0.0f);
            float v10 = fmaxf(acc[mt][nt][2] + bi0, 0.0f);
            float v11 = fmaxf(acc[mt][nt][3] + bi1, 0.0f);
            if (SPLIT_OUT) {
                __nv_bfloat16 h0, l0, h1, l1;
                split_bf16(v00, h0, l0); split_bf16(v01, h1, l1);
                *(__nv_bfloat162*)(out_hi + (size_t)r0 * 256 + c0) = __nv_bfloat162(h0, h1);
                *(__nv_bfloat162*)(out_lo + (size_t)r0 * 256 + c0) = __nv_bfloat162(l0, l1);
                split_bf16(v10, h0, l0); split_bf16(v11, h1, l1);
                *(__nv_bfloat162*)(out_hi + (size_t)(r0 + 8) * 256 + c0) = __nv_bfloat162(h0, h1);
                *(__nv_bfloat162*)(out_lo + (size_t)(r0 + 8) * 256 + c0) = __nv_bfloat162(l0, l1);
            } else {
                *(float2*)(out_f32 + (size_t)r0 * 256 + c0)       = make_float2(v00, v01);
                *(float2*)(out_f32 + (size_t)(r0 + 8) * 256 + c0) = make_float2(v10, v11);
            }
        }
    }
}

// ---------------------------------------------------------------------------
extern "C" void kernel_launch(void* const* d_in, const int* in_sizes, int n_in,
                              void* d_out, int out_size)
{
    const float* xyz1 = (const float*)d_in[0];
    const float* xyz2 = (const float*)d_in[1];
    const float* fea1 = (const float*)d_in[2];
    const float* fea2 = (const float*)d_in[3];
    const float* W1   = (const float*)d_in[4];
    const float* b1   = (const float*)d_in[5];
    const float* W2   = (const float*)d_in[6];
    const float* b2   = (const float*)d_in[7];
    float* out        = (float*)d_out;

    __nv_bfloat16 *f1h, *f1l, *ith, *itl, *hdh, *hdl, *w1h, *w1l, *w2h, *w2l;
    cudaGetSymbolAddress((void**)&f1h, g_fea1_hi);
    cudaGetSymbolAddress((void**)&f1l, g_fea1_lo);
    cudaGetSymbolAddress((void**)&ith, g_interp_hi);
    cudaGetSymbolAddress((void**)&itl, g_interp_lo);
    cudaGetSymbolAddress((void**)&hdh, g_hidden_hi);
    cudaGetSymbolAddress((void**)&hdl, g_hidden_lo);
    cudaGetSymbolAddress((void**)&w1h, g_w1t_hi);
    cudaGetSymbolAddress((void**)&w1l, g_w1t_lo);
    cudaGetSymbolAddress((void**)&w2h, g_w2t_hi);
    cudaGetSymbolAddress((void**)&w2l, g_w2t_lo);

    cudaFuncSetAttribute(gemm_bf16x3_kernel<CIN, true, true>,
                         cudaFuncAttributeMaxDynamicSharedMemorySize, SM_TOTAL);
    cudaFuncSetAttribute(gemm_bf16x3_kernel<CH, false, false>,
                         cudaFuncAttributeMaxDynamicSharedMemorySize, SM_TOTAL);

    // 1) fused: knn+interp | fea1 split | W1/W2 splits
    prep_knn_kernel<<<GRID_TOTAL, 256>>>(xyz1, xyz2, fea1, fea2, W1, W2);

    // 2) hidden = ReLU([fea1|interp] @ W1 + b1) -> bf16 hi/lo
    {
        dim3 grid(2, MTOT / 128);
        gemm_bf16x3_kernel<CIN, true, true><<<grid, 256, SM_TOTAL>>>(
            f1h, f1l, ith, itl, w1h, w1l, b1, nullptr, hdh, hdl);
    }

    // 3) out = ReLU(hidden @ W2 + b2) -> fp32
    {
        dim3 grid(2, MTOT / 128);
        gemm_bf16x3_kernel<CH, false, false><<<grid, 256, SM_TOTAL>>>(
            hdh, hdl, nullptr, nullptr, w2h, w2l, b2, out, nullptr, nullptr);
    }
}